// round 6
// baseline (speedup 1.0000x reference)
#include <cuda_runtime.h>

// Problem constants
#define NROWS 8192
#define DIN   1024
#define DHID  16384
#define TOPK  32
#define NCAND 48     // candidate margin for exact re-ranking

// ---------------------------------------------------------------------------
// Device scratch (static; no allocations allowed)
// ---------------------------------------------------------------------------
__device__ float g_wdecT[(size_t)DHID * DIN];     // 64 MB: W_dec transposed [DHID, DIN]
__device__ float g_tv[NROWS * TOPK];              // selected top-k values per row
__device__ int   g_ti[NROWS * TOPK];              // selected top-k indices per row
__device__ float g_cv[NROWS * NCAND];             // candidate values (fp32 z~)
__device__ int   g_ci[NROWS * NCAND];             // candidate indices
__device__ float g_zfb[(size_t)NROWS * DHID];     // 512 MB fallback z (if out lacks z)

// ---------------------------------------------------------------------------
// W_dec [DIN, DHID] row-major  ->  g_wdecT [DHID, DIN] row-major
// ---------------------------------------------------------------------------
__global__ void transpose_kernel(const float* __restrict__ Wd, float* __restrict__ WT)
{
    __shared__ float t[32][33];
    const int h0 = blockIdx.x << 5;
    const int i0 = blockIdx.y << 5;
    const int tx = threadIdx.x;
    const int ty = threadIdx.y;
#pragma unroll
    for (int r = 0; r < 32; r += 8)
        t[ty + r][tx] = Wd[(size_t)(i0 + ty + r) * DHID + h0 + tx];
    __syncthreads();
#pragma unroll
    for (int r = 0; r < 32; r += 8)
        WT[(size_t)(h0 + ty + r) * DIN + i0 + tx] = t[tx][ty + r];
}

// ---------------------------------------------------------------------------
// Encoder GEMM: Z[n][h] = relu( dot(X[n,:], W[h,:]) )   (fp32 SIMT, NT)
// 128x128 tile, BK=16, 256 threads, 8x8 per thread, double-buffered smem.
// ---------------------------------------------------------------------------
__global__ __launch_bounds__(256) void enc_gemm_kernel(const float* __restrict__ X,
                                                       const float* __restrict__ W,
                                                       float* __restrict__ Z)
{
    __shared__ float As[2][16][132];
    __shared__ float Bs[2][16][132];

    const int tid = threadIdx.x;
    const int lr  = tid >> 1;
    const int lk  = (tid & 1) << 3;

    const float* gA = X + (size_t)((blockIdx.y << 7) + lr) * DIN + lk;
    const float* gB = W + (size_t)((blockIdx.x << 7) + lr) * DIN + lk;

    float4 pa0 = *(const float4*)(gA);
    float4 pa1 = *(const float4*)(gA + 4);
    float4 pb0 = *(const float4*)(gB);
    float4 pb1 = *(const float4*)(gB + 4);

    As[0][lk + 0][lr] = pa0.x; As[0][lk + 1][lr] = pa0.y;
    As[0][lk + 2][lr] = pa0.z; As[0][lk + 3][lr] = pa0.w;
    As[0][lk + 4][lr] = pa1.x; As[0][lk + 5][lr] = pa1.y;
    As[0][lk + 6][lr] = pa1.z; As[0][lk + 7][lr] = pa1.w;
    Bs[0][lk + 0][lr] = pb0.x; Bs[0][lk + 1][lr] = pb0.y;
    Bs[0][lk + 2][lr] = pb0.z; Bs[0][lk + 3][lr] = pb0.w;
    Bs[0][lk + 4][lr] = pb1.x; Bs[0][lk + 5][lr] = pb1.y;
    Bs[0][lk + 6][lr] = pb1.z; Bs[0][lk + 7][lr] = pb1.w;
    __syncthreads();

    float acc[8][8];
#pragma unroll
    for (int i = 0; i < 8; ++i)
#pragma unroll
        for (int j = 0; j < 8; ++j) acc[i][j] = 0.0f;

    const int trow = (tid >> 4) << 3;
    const int tcol = (tid & 15) << 3;

    int buf = 0;
    const int NKT = DIN / 16;
    for (int kt = 1; kt <= NKT; ++kt) {
        if (kt < NKT) {
            const float* pA = gA + (kt << 4);
            const float* pB = gB + (kt << 4);
            pa0 = *(const float4*)(pA);
            pa1 = *(const float4*)(pA + 4);
            pb0 = *(const float4*)(pB);
            pb1 = *(const float4*)(pB + 4);
        }
#pragma unroll
        for (int kk = 0; kk < 16; ++kk) {
            float4 a0 = *(const float4*)&As[buf][kk][trow];
            float4 a1 = *(const float4*)&As[buf][kk][trow + 4];
            float4 b0 = *(const float4*)&Bs[buf][kk][tcol];
            float4 b1 = *(const float4*)&Bs[buf][kk][tcol + 4];
            float a[8] = {a0.x, a0.y, a0.z, a0.w, a1.x, a1.y, a1.z, a1.w};
            float b[8] = {b0.x, b0.y, b0.z, b0.w, b1.x, b1.y, b1.z, b1.w};
#pragma unroll
            for (int i = 0; i < 8; ++i)
#pragma unroll
                for (int j = 0; j < 8; ++j)
                    acc[i][j] += a[i] * b[j];
        }
        if (kt < NKT) {
            const int nb = buf ^ 1;
            As[nb][lk + 0][lr] = pa0.x; As[nb][lk + 1][lr] = pa0.y;
            As[nb][lk + 2][lr] = pa0.z; As[nb][lk + 3][lr] = pa0.w;
            As[nb][lk + 4][lr] = pa1.x; As[nb][lk + 5][lr] = pa1.y;
            As[nb][lk + 6][lr] = pa1.z; As[nb][lk + 7][lr] = pa1.w;
            Bs[nb][lk + 0][lr] = pb0.x; Bs[nb][lk + 1][lr] = pb0.y;
            Bs[nb][lk + 2][lr] = pb0.z; Bs[nb][lk + 3][lr] = pb0.w;
            Bs[nb][lk + 4][lr] = pb1.x; Bs[nb][lk + 5][lr] = pb1.y;
            Bs[nb][lk + 6][lr] = pb1.z; Bs[nb][lk + 7][lr] = pb1.w;
            __syncthreads();
        }
        buf ^= 1;
    }

    float* Zp = Z + (size_t)((blockIdx.y << 7) + trow) * DHID + (blockIdx.x << 7) + tcol;
#pragma unroll
    for (int i = 0; i < 8; ++i) {
        float4 r0, r1;
        r0.x = fmaxf(acc[i][0], 0.0f); r0.y = fmaxf(acc[i][1], 0.0f);
        r0.z = fmaxf(acc[i][2], 0.0f); r0.w = fmaxf(acc[i][3], 0.0f);
        r1.x = fmaxf(acc[i][4], 0.0f); r1.y = fmaxf(acc[i][5], 0.0f);
        r1.z = fmaxf(acc[i][6], 0.0f); r1.w = fmaxf(acc[i][7], 0.0f);
        *(float4*)(Zp + (size_t)i * DHID)     = r0;
        *(float4*)(Zp + (size_t)i * DHID + 4) = r1;
    }
}

// ---------------------------------------------------------------------------
// Per-row top-NCAND candidate extraction (one CTA per row, 256 threads, row in
// 64 KB smem). Interleaved ownership -> conflict-free LDS. Also zero-fills the
// dense z_sparse row (scatter happens later in refine_kernel).
// ---------------------------------------------------------------------------
__global__ __launch_bounds__(256) void topk_kernel(const float* __restrict__ Z,
                                                   float* __restrict__ Zsp,
                                                   float* __restrict__ cvg,
                                                   int* __restrict__ cig,
                                                   int write_zsp)
{
    extern __shared__ float s[];                 // DHID floats = 64 KB
    __shared__ float wv[8];
    __shared__ int   wi[8];
    __shared__ float topv[NCAND];
    __shared__ int   topi[NCAND];

    const int tid = threadIdx.x;
    const size_t rowoff = (size_t)blockIdx.x * DHID;

    const float4* zr = (const float4*)(Z + rowoff);
    float4* sv4 = (float4*)s;
#pragma unroll
    for (int j = 0; j < 16; ++j) {
        const int q = j * 256 + tid;
        sv4[q] = zr[q];
    }
    if (write_zsp) {
        float4 zero = make_float4(0.f, 0.f, 0.f, 0.f);
        float4* zo = (float4*)(Zsp + rowoff);
#pragma unroll
        for (int j = 0; j < 16; ++j)
            zo[j * 256 + tid] = zero;
    }
    __syncthreads();

    float lv = -1.0f; int li = tid;
#pragma unroll 8
    for (int j = 0; j < 64; ++j) {
        const int idx = tid + (j << 8);
        const float v = s[idx];
        if (v > lv) { lv = v; li = idx; }
    }

    for (int it = 0; it < NCAND; ++it) {
        float v = lv; int i = li;
#pragma unroll
        for (int o = 16; o; o >>= 1) {
            const float v2 = __shfl_down_sync(0xFFFFFFFFu, v, o);
            const int   i2 = __shfl_down_sync(0xFFFFFFFFu, i, o);
            if (v2 > v || (v2 == v && i2 < i)) { v = v2; i = i2; }
        }
        if ((tid & 31) == 0) { wv[tid >> 5] = v; wi[tid >> 5] = i; }
        __syncthreads();

        float bv = wv[0]; int bi = wi[0];
#pragma unroll
        for (int w = 1; w < 8; ++w) {
            const float v2 = wv[w]; const int i2 = wi[w];
            if (v2 > bv || (v2 == bv && i2 < bi)) { bv = v2; bi = i2; }
        }
        if (tid == 0) { topv[it] = bv; topi[it] = bi; }

        if ((bi & 255) == tid) {
            s[bi] = -1.0f;
            lv = -1.0f; li = tid;
#pragma unroll 8
            for (int j = 0; j < 64; ++j) {
                const int idx = tid + (j << 8);
                const float vv = s[idx];
                if (vv > lv) { lv = vv; li = idx; }
            }
        }
        __syncthreads();
    }

    if (tid < NCAND) {
        const int o = blockIdx.x * NCAND + tid;
        cvg[o] = topv[tid];
        cig[o] = topi[tid];
    }
}

// ---------------------------------------------------------------------------
// Exact re-rank: recompute the NCAND candidate dot products per row in fp64,
// select the true top-TOPK, write (val, idx) and scatter z_sparse.
// One CTA per row, 256 threads; each warp handles NCAND/8 = 6 candidates.
// ---------------------------------------------------------------------------
__global__ __launch_bounds__(256) void refine_kernel(const float* __restrict__ X,
                                                     const float* __restrict__ W,
                                                     const float* __restrict__ cvg,
                                                     const int* __restrict__ cig,
                                                     float* __restrict__ Zsp,
                                                     float* __restrict__ tvg,
                                                     int* __restrict__ tig,
                                                     int write_zsp)
{
    __shared__ float  sx[DIN];
    __shared__ double dres[NCAND];
    __shared__ float  scv[NCAND];
    __shared__ int    sci[NCAND];

    const int tid  = threadIdx.x;
    const int row  = blockIdx.x;
    const int lane = tid & 31;
    const int w    = tid >> 5;

    for (int j = tid; j < DIN; j += 256)
        sx[j] = X[(size_t)row * DIN + j];
    if (tid < NCAND) {
        scv[tid] = cvg[row * NCAND + tid];
        sci[tid] = cig[row * NCAND + tid];
    }
    __syncthreads();

    for (int c = w; c < NCAND; c += 8) {
        const float* wr = W + ((size_t)sci[c] << 10);
        double a0 = 0.0, a1 = 0.0;                    // 2 accumulators: shorten DFMA chain
#pragma unroll
        for (int j = 0; j < DIN / 64; ++j) {          // 16 iterations, 2 lanes' worth each
            const int e = lane + (j << 6);
            a0 += (double)sx[e]      * (double)wr[e];
            a1 += (double)sx[e + 32] * (double)wr[e + 32];
        }
        double acc = a0 + a1;
#pragma unroll
        for (int o = 16; o; o >>= 1)
            acc += __shfl_down_sync(0xFFFFFFFFu, acc, o);
        if (lane == 0) dres[c] = acc;
    }
    __syncthreads();

    if (tid < NCAND) {
        const double v = dres[tid];
        int rank = 0;
#pragma unroll 8
        for (int j = 0; j < NCAND; ++j) {
            const double u = dres[j];
            if (u > v || (u == v && j < tid)) ++rank;
        }
        if (rank < TOPK) {
            tvg[row * TOPK + rank] = scv[tid];
            tig[row * TOPK + rank] = sci[tid];
            if (write_zsp)
                Zsp[(size_t)row * DHID + sci[tid]] = scv[tid];
        }
    }
}

// ---------------------------------------------------------------------------
// Decoder: x_hat[n,:] = sum_k tv[n,k] * WdT[ti[n,k], :]   (one CTA per row)
// ---------------------------------------------------------------------------
__global__ __launch_bounds__(256) void dec_kernel(const float* __restrict__ WT,
                                                  const float* __restrict__ tvg,
                                                  const int* __restrict__ tig,
                                                  float* __restrict__ xhat)
{
    __shared__ float sv[TOPK];
    __shared__ int   si[TOPK];
    const int tid = threadIdx.x;
    const int row = blockIdx.x;
    if (tid < TOPK) {
        sv[tid] = tvg[row * TOPK + tid];
        si[tid] = tig[row * TOPK + tid];
    }
    __syncthreads();

    const int c = tid << 2;
    float4 acc = make_float4(0.f, 0.f, 0.f, 0.f);
#pragma unroll
    for (int k = 0; k < TOPK; ++k) {
        const float v = sv[k];
        const float4 w = *(const float4*)(WT + ((size_t)si[k] << 10) + c);
        acc.x += v * w.x; acc.y += v * w.y;
        acc.z += v * w.z; acc.w += v * w.w;
    }
    *(float4*)(xhat + ((size_t)row << 10) + c) = acc;
}

// ---------------------------------------------------------------------------
// active = mean_n ( count_k(top-k val > 0) )
// ---------------------------------------------------------------------------
__global__ void active_kernel(const float* __restrict__ tvg, float* __restrict__ act)
{
    __shared__ int sc[256];
    const int tid = threadIdx.x;
    int c = 0;
    for (int i = tid; i < NROWS * TOPK; i += 256)
        c += (tvg[i] > 0.0f) ? 1 : 0;
    sc[tid] = c;
    __syncthreads();
    for (int o = 128; o; o >>= 1) {
        if (tid < o) sc[tid] += sc[tid + o];
        __syncthreads();
    }
    if (tid == 0) act[0] = (float)sc[0] / (float)NROWS;
}

// ---------------------------------------------------------------------------
// Launch
// ---------------------------------------------------------------------------
extern "C" void kernel_launch(void* const* d_in, const int* in_sizes, int n_in,
                              void* d_out, int out_size)
{
    (void)in_sizes; (void)n_in;
    const float* x  = (const float*)d_in[0];
    const float* We = (const float*)d_in[1];
    const float* Wd = (const float*)d_in[2];
    float* out = (float*)d_out;

    float* g_wt;  cudaGetSymbolAddress((void**)&g_wt,  g_wdecT);
    float* g_tvp; cudaGetSymbolAddress((void**)&g_tvp, g_tv);
    int*   g_tip; cudaGetSymbolAddress((void**)&g_tip, g_ti);
    float* g_cvp; cudaGetSymbolAddress((void**)&g_cvp, g_cv);
    int*   g_cip; cudaGetSymbolAddress((void**)&g_cip, g_ci);
    float* g_zp;  cudaGetSymbolAddress((void**)&g_zp,  g_zfb);

    const long long XH = (long long)NROWS * DIN;        // 8388608
    const long long ZZ = (long long)NROWS * DHID;       // 134217728
    const long long os = (long long)out_size;

    // Output layout: [x_hat | z_sparse | z | active] flat concat.
    float* xhat = out;
    float* zsp  = nullptr;
    float* z    = nullptr;
    float* act  = nullptr;
    if (os >= XH + 2 * ZZ) {
        zsp = out + XH;
        z   = out + XH + ZZ;
        if (os > XH + 2 * ZZ) act = out + XH + 2 * ZZ;
    } else if (os >= XH + ZZ) {
        zsp = out + XH;
    }
    if (!z) z = g_zp;

    cudaFuncSetAttribute(topk_kernel,
                         cudaFuncAttributeMaxDynamicSharedMemorySize, DHID * 4);

    // 1. transpose W_dec (independent; needed by decoder)
    transpose_kernel<<<dim3(DHID / 32, DIN / 32), dim3(32, 8)>>>(Wd, g_wt);

    // 2. encoder GEMM + relu -> z (written directly into output region)
    enc_gemm_kernel<<<dim3(DHID / 128, NROWS / 128), 256>>>(x, We, z);

    // 3. per-row top-NCAND candidates (+ zero-fill z_sparse)
    topk_kernel<<<NROWS, 256, DHID * 4>>>(z, zsp ? zsp : z, g_cvp, g_cip,
                                          zsp != nullptr ? 1 : 0);

    // 4. exact fp64 re-rank of candidates -> true top-32, scatter z_sparse
    refine_kernel<<<NROWS, 256>>>(x, We, g_cvp, g_cip,
                                  zsp ? zsp : z, g_tvp, g_tip,
                                  zsp != nullptr ? 1 : 0);

    // 5. sparse decoder -> x_hat
    dec_kernel<<<NROWS, 256>>>(g_wt, g_tvp, g_tip, xhat);

    // 6. active scalar
    if (act) active_kernel<<<1, 256>>>(g_tvp, act);
}

// round 7
// speedup vs baseline: 1.1750x; 1.1750x over previous
#include <cuda_runtime.h>
#include <cuda_bf16.h>
#include <cstdint>

// Problem constants
#define NROWS 8192
#define DIN   1024
#define DHID  16384
#define TOPK  32
#define NCAND 48     // candidate margin for exact re-ranking

// ---------------------------------------------------------------------------
// Device scratch (static; no allocations allowed)
// ---------------------------------------------------------------------------
__device__ __nv_bfloat16 g_xhi[(size_t)NROWS * DIN];   // 16 MB
__device__ __nv_bfloat16 g_xlo[(size_t)NROWS * DIN];   // 16 MB
__device__ __nv_bfloat16 g_whi[(size_t)DHID * DIN];    // 32 MB
__device__ __nv_bfloat16 g_wlo[(size_t)DHID * DIN];    // 32 MB
__device__ float g_wdecT[(size_t)DHID * DIN];          // 64 MB
__device__ float g_tv[NROWS * TOPK];
__device__ int   g_ti[NROWS * TOPK];
__device__ float g_cv[NROWS * NCAND];
__device__ int   g_ci[NROWS * NCAND];
__device__ float g_zfb[(size_t)NROWS * DHID];          // fallback z

// ---------------------------------------------------------------------------
// fp32 -> (bf16 hi, bf16 lo) split:  hi = bf16(v), lo = bf16(v - f32(hi))
// ---------------------------------------------------------------------------
__global__ void split_kernel(const float* __restrict__ in,
                             __nv_bfloat16* __restrict__ hi,
                             __nv_bfloat16* __restrict__ lo, int n4)
{
    const int i = blockIdx.x * blockDim.x + threadIdx.x;
    if (i >= n4) return;
    const float4 v = ((const float4*)in)[i];
    float vv[4] = {v.x, v.y, v.z, v.w};
    unsigned short h[4], l[4];
#pragma unroll
    for (int j = 0; j < 4; ++j) {
        __nv_bfloat16 hb = __float2bfloat16(vv[j]);
        __nv_bfloat16 lb = __float2bfloat16(vv[j] - __bfloat162float(hb));
        h[j] = *reinterpret_cast<unsigned short*>(&hb);
        l[j] = *reinterpret_cast<unsigned short*>(&lb);
    }
    ((ushort4*)hi)[i] = make_ushort4(h[0], h[1], h[2], h[3]);
    ((ushort4*)lo)[i] = make_ushort4(l[0], l[1], l[2], l[3]);
}

// ---------------------------------------------------------------------------
// W_dec [DIN, DHID] row-major  ->  g_wdecT [DHID, DIN] row-major
// ---------------------------------------------------------------------------
__global__ void transpose_kernel(const float* __restrict__ Wd, float* __restrict__ WT)
{
    __shared__ float t[32][33];
    const int h0 = blockIdx.x << 5;
    const int i0 = blockIdx.y << 5;
    const int tx = threadIdx.x;
    const int ty = threadIdx.y;
#pragma unroll
    for (int r = 0; r < 32; r += 8)
        t[ty + r][tx] = Wd[(size_t)(i0 + ty + r) * DHID + h0 + tx];
    __syncthreads();
#pragma unroll
    for (int r = 0; r < 32; r += 8)
        WT[(size_t)(h0 + ty + r) * DIN + i0 + tx] = t[tx][ty + r];
}

// ---------------------------------------------------------------------------
// Tensor-core encoder: Z = relu( Xhi*Whi^T + Xhi*Wlo^T + Xlo*Whi^T )
// Warp-level mma.m16n8k16.bf16, CTA tile 128x128, warp tile 64x32, BK=32.
// Virtual K = 3*1024 via phase-switched pointers. Depth-2 LDG prefetch,
// double-buffered smem, 80B-padded rows (conflict-free ldmatrix).
// ---------------------------------------------------------------------------
__device__ __forceinline__ void ldsm4(uint32_t* r, uint32_t addr) {
    asm volatile("ldmatrix.sync.aligned.m8n8.x4.shared.b16 {%0,%1,%2,%3}, [%4];\n"
        : "=r"(r[0]), "=r"(r[1]), "=r"(r[2]), "=r"(r[3]) : "r"(addr));
}
__device__ __forceinline__ void ldsm2(uint32_t* r, uint32_t addr) {
    asm volatile("ldmatrix.sync.aligned.m8n8.x2.shared.b16 {%0,%1}, [%2];\n"
        : "=r"(r[0]), "=r"(r[1]) : "r"(addr));
}
__device__ __forceinline__ void mma16816(float* c, const uint32_t* a, const uint32_t* b) {
    asm volatile(
        "mma.sync.aligned.m16n8k16.row.col.f32.bf16.bf16.f32 "
        "{%0,%1,%2,%3}, {%4,%5,%6,%7}, {%8,%9}, {%0,%1,%2,%3};\n"
        : "+f"(c[0]), "+f"(c[1]), "+f"(c[2]), "+f"(c[3])
        : "r"(a[0]), "r"(a[1]), "r"(a[2]), "r"(a[3]), "r"(b[0]), "r"(b[1]));
}

#define SM_STRIDE 80           // 64B data + 16B pad per row (conflict-free)
#define SM_BUF    (128 * SM_STRIDE)
#define NCHUNK    96           // virtual K=3072 / BK=32

__global__ __launch_bounds__(256) void enc_gemm_bf16x3(
    const __nv_bfloat16* __restrict__ Xhi, const __nv_bfloat16* __restrict__ Xlo,
    const __nv_bfloat16* __restrict__ Whi, const __nv_bfloat16* __restrict__ Wlo,
    float* __restrict__ Z)
{
    __shared__ __align__(16) unsigned char smA[2 * SM_BUF];
    __shared__ __align__(16) unsigned char smB[2 * SM_BUF];

    const int tid  = threadIdx.x;
    const int lane = tid & 31;
    const int warp = tid >> 5;
    const int Mw = (warp >> 2) << 6;    // 0 / 64
    const int Nw = (warp & 3) << 5;     // 0 / 32 / 64 / 96
    const int bm = blockIdx.y << 7;
    const int bn = blockIdx.x << 7;

    // gmem<->smem chunk mapping: ids tid, tid+256 -> (m, kc)
    const int m0  = tid >> 2;           // 0..63
    const int m1  = m0 + 64;            // 64..127
    const int kc  = tid & 3;            // 16B chunk within 64B row

    const uint32_t sA = (uint32_t)__cvta_generic_to_shared(smA);
    const uint32_t sB = (uint32_t)__cvta_generic_to_shared(smB);

    const uint32_t stsA0 = sA + m0 * SM_STRIDE + kc * 16;
    const uint32_t stsA1 = sA + m1 * SM_STRIDE + kc * 16;
    const uint32_t stsB0 = sB + m0 * SM_STRIDE + kc * 16;
    const uint32_t stsB1 = sB + m1 * SM_STRIDE + kc * 16;

    // ldmatrix per-thread base offsets
    const int tm = (lane & 7) + ((lane >> 3) & 1) * 8;   // m within 16-tile
    const int tk = lane >> 4;                            // k-half (0/1)
    const uint32_t aBase = sA + (Mw + tm) * SM_STRIDE + tk * 16;
    const int tb = lane & 15;
    const uint32_t bBase = sB + (Nw + (tb & 7)) * SM_STRIDE + (tb >> 3) * 16;

    float acc[4][4][4];
#pragma unroll
    for (int mi = 0; mi < 4; ++mi)
#pragma unroll
        for (int ni = 0; ni < 4; ++ni)
#pragma unroll
            for (int e = 0; e < 4; ++e) acc[mi][ni][e] = 0.0f;

    float4 ra[2][2], rb[2][2];

    // --- LDG for chunk c into reg set s ---
#define LDG_CHUNK(c, s)                                                          \
    do {                                                                         \
        const int ph = (c) >> 5;                                                 \
        const int k0 = ((c) & 31) << 5;                                          \
        const __nv_bfloat16* Ap = (ph == 2) ? Xlo : Xhi;                         \
        const __nv_bfloat16* Bp = (ph == 1) ? Wlo : Whi;                         \
        ra[s][0] = *(const float4*)(Ap + (size_t)(bm + m0) * DIN + k0 + kc * 8); \
        ra[s][1] = *(const float4*)(Ap + (size_t)(bm + m1) * DIN + k0 + kc * 8); \
        rb[s][0] = *(const float4*)(Bp + (size_t)(bn + m0) * DIN + k0 + kc * 8); \
        rb[s][1] = *(const float4*)(Bp + (size_t)(bn + m1) * DIN + k0 + kc * 8); \
    } while (0)

#define STS_CHUNK(bufsel, s)                                                     \
    do {                                                                         \
        const uint32_t off = (bufsel) * SM_BUF;                                  \
        *(float4*)(smA + off + m0 * SM_STRIDE + kc * 16) = ra[s][0];             \
        *(float4*)(smA + off + m1 * SM_STRIDE + kc * 16) = ra[s][1];             \
        *(float4*)(smB + off + m0 * SM_STRIDE + kc * 16) = rb[s][0];             \
        *(float4*)(smB + off + m1 * SM_STRIDE + kc * 16) = rb[s][1];             \
    } while (0)

    (void)stsA0; (void)stsA1; (void)stsB0; (void)stsB1;

    // prologue
    LDG_CHUNK(0, 0);
    STS_CHUNK(0, 0);
    LDG_CHUNK(1, 1);
    __syncthreads();

    int buf = 0;
    for (int c = 0; c < NCHUNK; ++c) {
        if (c + 2 < NCHUNK) LDG_CHUNK(c + 2, (c & 1));

        // compute on smem[buf]: 2 k16-steps
        const uint32_t aB = aBase + buf * SM_BUF;
        const uint32_t bB = bBase + buf * SM_BUF;
#pragma unroll
        for (int ks = 0; ks < 2; ++ks) {
            uint32_t af[4][4], bf[4][2];
#pragma unroll
            for (int mi = 0; mi < 4; ++mi)
                ldsm4(af[mi], aB + mi * (16 * SM_STRIDE) + ks * 32);
#pragma unroll
            for (int ni = 0; ni < 4; ++ni)
                ldsm2(bf[ni], bB + ni * (8 * SM_STRIDE) + ks * 32);
#pragma unroll
            for (int mi = 0; mi < 4; ++mi)
#pragma unroll
                for (int ni = 0; ni < 4; ++ni)
                    mma16816(acc[mi][ni], af[mi], bf[ni]);
        }

        if (c + 1 < NCHUNK) {
            STS_CHUNK(buf ^ 1, ((c + 1) & 1));
            __syncthreads();
        }
        buf ^= 1;
    }

    // epilogue: relu + store (c0,c1 at row er; c2,c3 at row er+8)
    const int er = lane >> 2;
    const int ec = (lane & 3) << 1;
#pragma unroll
    for (int mi = 0; mi < 4; ++mi) {
#pragma unroll
        for (int ni = 0; ni < 4; ++ni) {
            const size_t row = (size_t)(bm + Mw + mi * 16 + er);
            const int    col = bn + Nw + ni * 8 + ec;
            float2 v0, v1;
            v0.x = fmaxf(acc[mi][ni][0], 0.0f);
            v0.y = fmaxf(acc[mi][ni][1], 0.0f);
            v1.x = fmaxf(acc[mi][ni][2], 0.0f);
            v1.y = fmaxf(acc[mi][ni][3], 0.0f);
            *(float2*)(Z + row * DHID + col)       = v0;
            *(float2*)(Z + (row + 8) * DHID + col) = v1;
        }
    }
#undef LDG_CHUNK
#undef STS_CHUNK
}

// ---------------------------------------------------------------------------
// Per-row top-NCAND candidate extraction (one CTA per row, 256 threads, row in
// 64 KB smem). Interleaved ownership -> conflict-free LDS. Also zero-fills the
// dense z_sparse row (scatter happens later in refine_kernel).
// ---------------------------------------------------------------------------
__global__ __launch_bounds__(256) void topk_kernel(const float* __restrict__ Z,
                                                   float* __restrict__ Zsp,
                                                   float* __restrict__ cvg,
                                                   int* __restrict__ cig,
                                                   int write_zsp)
{
    extern __shared__ float s[];
    __shared__ float wv[8];
    __shared__ int   wi[8];
    __shared__ float topv[NCAND];
    __shared__ int   topi[NCAND];

    const int tid = threadIdx.x;
    const size_t rowoff = (size_t)blockIdx.x * DHID;

    const float4* zr = (const float4*)(Z + rowoff);
    float4* sv4 = (float4*)s;
#pragma unroll
    for (int j = 0; j < 16; ++j) {
        const int q = j * 256 + tid;
        sv4[q] = zr[q];
    }
    if (write_zsp) {
        float4 zero = make_float4(0.f, 0.f, 0.f, 0.f);
        float4* zo = (float4*)(Zsp + rowoff);
#pragma unroll
        for (int j = 0; j < 16; ++j)
            zo[j * 256 + tid] = zero;
    }
    __syncthreads();

    float lv = -1.0f; int li = tid;
#pragma unroll 8
    for (int j = 0; j < 64; ++j) {
        const int idx = tid + (j << 8);
        const float v = s[idx];
        if (v > lv) { lv = v; li = idx; }
    }

    for (int it = 0; it < NCAND; ++it) {
        float v = lv; int i = li;
#pragma unroll
        for (int o = 16; o; o >>= 1) {
            const float v2 = __shfl_down_sync(0xFFFFFFFFu, v, o);
            const int   i2 = __shfl_down_sync(0xFFFFFFFFu, i, o);
            if (v2 > v || (v2 == v && i2 < i)) { v = v2; i = i2; }
        }
        if ((tid & 31) == 0) { wv[tid >> 5] = v; wi[tid >> 5] = i; }
        __syncthreads();

        float bv = wv[0]; int bi = wi[0];
#pragma unroll
        for (int w = 1; w < 8; ++w) {
            const float v2 = wv[w]; const int i2 = wi[w];
            if (v2 > bv || (v2 == bv && i2 < bi)) { bv = v2; bi = i2; }
        }
        if (tid == 0) { topv[it] = bv; topi[it] = bi; }

        if ((bi & 255) == tid) {
            s[bi] = -1.0f;
            lv = -1.0f; li = tid;
#pragma unroll 8
            for (int j = 0; j < 64; ++j) {
                const int idx = tid + (j << 8);
                const float vv = s[idx];
                if (vv > lv) { lv = vv; li = idx; }
            }
        }
        __syncthreads();
    }

    if (tid < NCAND) {
        const int o = blockIdx.x * NCAND + tid;
        cvg[o] = topv[tid];
        cig[o] = topi[tid];
    }
}

// ---------------------------------------------------------------------------
// Exact re-rank: recompute the NCAND candidate dot products per row in fp64
// (from the original fp32 inputs), select the true top-TOPK, write (val, idx)
// and scatter z_sparse.
// ---------------------------------------------------------------------------
__global__ __launch_bounds__(256) void refine_kernel(const float* __restrict__ X,
                                                     const float* __restrict__ W,
                                                     const float* __restrict__ cvg,
                                                     const int* __restrict__ cig,
                                                     float* __restrict__ Zsp,
                                                     float* __restrict__ tvg,
                                                     int* __restrict__ tig,
                                                     int write_zsp)
{
    __shared__ float  sx[DIN];
    __shared__ double dres[NCAND];
    __shared__ float  scv[NCAND];
    __shared__ int    sci[NCAND];

    const int tid  = threadIdx.x;
    const int row  = blockIdx.x;
    const int lane = tid & 31;
    const int w    = tid >> 5;

    for (int j = tid; j < DIN; j += 256)
        sx[j] = X[(size_t)row * DIN + j];
    if (tid < NCAND) {
        scv[tid] = cvg[row * NCAND + tid];
        sci[tid] = cig[row * NCAND + tid];
    }
    __syncthreads();

    for (int c = w; c < NCAND; c += 8) {
        const float* wr = W + ((size_t)sci[c] << 10);
        double a0 = 0.0, a1 = 0.0;
#pragma unroll
        for (int j = 0; j < DIN / 64; ++j) {
            const int e = lane + (j << 6);
            a0 += (double)sx[e]      * (double)wr[e];
            a1 += (double)sx[e + 32] * (double)wr[e + 32];
        }
        double acc = a0 + a1;
#pragma unroll
        for (int o = 16; o; o >>= 1)
            acc += __shfl_down_sync(0xFFFFFFFFu, acc, o);
        if (lane == 0) dres[c] = acc;
    }
    __syncthreads();

    if (tid < NCAND) {
        const double v = dres[tid];
        int rank = 0;
#pragma unroll 8
        for (int j = 0; j < NCAND; ++j) {
            const double u = dres[j];
            if (u > v || (u == v && j < tid)) ++rank;
        }
        if (rank < TOPK) {
            tvg[row * TOPK + rank] = scv[tid];
            tig[row * TOPK + rank] = sci[tid];
            if (write_zsp)
                Zsp[(size_t)row * DHID + sci[tid]] = scv[tid];
        }
    }
}

// ---------------------------------------------------------------------------
// Decoder: x_hat[n,:] = sum_k tv[n,k] * WdT[ti[n,k], :]   (one CTA per row)
// ---------------------------------------------------------------------------
__global__ __launch_bounds__(256) void dec_kernel(const float* __restrict__ WT,
                                                  const float* __restrict__ tvg,
                                                  const int* __restrict__ tig,
                                                  float* __restrict__ xhat)
{
    __shared__ float sv[TOPK];
    __shared__ int   si[TOPK];
    const int tid = threadIdx.x;
    const int row = blockIdx.x;
    if (tid < TOPK) {
        sv[tid] = tvg[row * TOPK + tid];
        si[tid] = tig[row * TOPK + tid];
    }
    __syncthreads();

    const int c = tid << 2;
    float4 acc = make_float4(0.f, 0.f, 0.f, 0.f);
#pragma unroll
    for (int k = 0; k < TOPK; ++k) {
        const float v = sv[k];
        const float4 w = *(const float4*)(WT + ((size_t)si[k] << 10) + c);
        acc.x += v * w.x; acc.y += v * w.y;
        acc.z += v * w.z; acc.w += v * w.w;
    }
    *(float4*)(xhat + ((size_t)row << 10) + c) = acc;
}

// ---------------------------------------------------------------------------
// active = mean_n ( count_k(top-k val > 0) )
// ---------------------------------------------------------------------------
__global__ void active_kernel(const float* __restrict__ tvg, float* __restrict__ act)
{
    __shared__ int sc[256];
    const int tid = threadIdx.x;
    int c = 0;
    for (int i = tid; i < NROWS * TOPK; i += 256)
        c += (tvg[i] > 0.0f) ? 1 : 0;
    sc[tid] = c;
    __syncthreads();
    for (int o = 128; o; o >>= 1) {
        if (tid < o) sc[tid] += sc[tid + o];
        __syncthreads();
    }
    if (tid == 0) act[0] = (float)sc[0] / (float)NROWS;
}

// ---------------------------------------------------------------------------
// Launch
// ---------------------------------------------------------------------------
extern "C" void kernel_launch(void* const* d_in, const int* in_sizes, int n_in,
                              void* d_out, int out_size)
{
    (void)in_sizes; (void)n_in;
    const float* x  = (const float*)d_in[0];
    const float* We = (const float*)d_in[1];
    const float* Wd = (const float*)d_in[2];
    float* out = (float*)d_out;

    __nv_bfloat16 *g_xh, *g_xl, *g_wh, *g_wl;
    cudaGetSymbolAddress((void**)&g_xh, g_xhi);
    cudaGetSymbolAddress((void**)&g_xl, g_xlo);
    cudaGetSymbolAddress((void**)&g_wh, g_whi);
    cudaGetSymbolAddress((void**)&g_wl, g_wlo);
    float* g_wt;  cudaGetSymbolAddress((void**)&g_wt,  g_wdecT);
    float* g_tvp; cudaGetSymbolAddress((void**)&g_tvp, g_tv);
    int*   g_tip; cudaGetSymbolAddress((void**)&g_tip, g_ti);
    float* g_cvp; cudaGetSymbolAddress((void**)&g_cvp, g_cv);
    int*   g_cip; cudaGetSymbolAddress((void**)&g_cip, g_ci);
    float* g_zp;  cudaGetSymbolAddress((void**)&g_zp,  g_zfb);

    const long long XH = (long long)NROWS * DIN;        // 8388608
    const long long ZZ = (long long)NROWS * DHID;       // 134217728
    const long long os = (long long)out_size;

    // Output layout: [x_hat | z_sparse | z | active] flat concat.
    float* xhat = out;
    float* zsp  = nullptr;
    float* z    = nullptr;
    float* act  = nullptr;
    if (os >= XH + 2 * ZZ) {
        zsp = out + XH;
        z   = out + XH + ZZ;
        if (os > XH + 2 * ZZ) act = out + XH + 2 * ZZ;
    } else if (os >= XH + ZZ) {
        zsp = out + XH;
    }
    if (!z) z = g_zp;

    cudaFuncSetAttribute(topk_kernel,
                         cudaFuncAttributeMaxDynamicSharedMemorySize, DHID * 4);

    // 1. bf16 hi/lo splits of X and W_enc
    split_kernel<<<(NROWS * DIN / 4 + 255) / 256, 256>>>(x, g_xh, g_xl, NROWS * DIN / 4);
    split_kernel<<<(DHID * DIN / 4 + 255) / 256, 256>>>(We, g_wh, g_wl, DHID * DIN / 4);

    // 2. transpose W_dec (independent; needed by decoder)
    transpose_kernel<<<dim3(DHID / 32, DIN / 32), dim3(32, 8)>>>(Wd, g_wt);

    // 3. tensor-core encoder GEMM (3-pass bf16 emulated fp32) + relu -> z
    enc_gemm_bf16x3<<<dim3(DHID / 128, NROWS / 128), 256>>>(g_xh, g_xl, g_wh, g_wl, z);

    // 4. per-row top-NCAND candidates (+ zero-fill z_sparse)
    topk_kernel<<<NROWS, 256, DHID * 4>>>(z, zsp ? zsp : z, g_cvp, g_cip,
                                          zsp != nullptr ? 1 : 0);

    // 5. exact fp64 re-rank of candidates -> true top-32, scatter z_sparse
    refine_kernel<<<NROWS, 256>>>(x, We, g_cvp, g_cip,
                                  zsp ? zsp : z, g_tvp, g_tip,
                                  zsp != nullptr ? 1 : 0);

    // 6. sparse decoder -> x_hat
    dec_kernel<<<NROWS, 256>>>(g_wt, g_tvp, g_tip, xhat);

    // 7. active scalar
    if (act) active_kernel<<<1, 256>>>(g_tvp, act);
}

// round 12
// speedup vs baseline: 1.4863x; 1.2649x over previous
#include <cuda_runtime.h>
#include <cuda_bf16.h>
#include <cstdint>

// Problem constants
#define NROWS 8192
#define DIN   1024
#define DHID  16384
#define TOPK  32
#define NCAND 48     // candidate margin for exact re-ranking

// ---------------------------------------------------------------------------
// Device scratch (static; no allocations allowed)
// ---------------------------------------------------------------------------
__device__ __nv_bfloat16 g_xhi[(size_t)NROWS * DIN];   // 16 MB
__device__ __nv_bfloat16 g_xlo[(size_t)NROWS * DIN];   // 16 MB
__device__ __nv_bfloat16 g_whi[(size_t)DHID * DIN];    // 32 MB
__device__ __nv_bfloat16 g_wlo[(size_t)DHID * DIN];    // 32 MB
__device__ float g_wdecT[(size_t)DHID * DIN];          // 64 MB
__device__ float g_tv[NROWS * TOPK];
__device__ int   g_ti[NROWS * TOPK];
__device__ float g_cv[NROWS * NCAND];
__device__ int   g_ci[NROWS * NCAND];
__device__ float g_zfb[(size_t)NROWS * DHID];          // fallback z

// ---------------------------------------------------------------------------
// fp32 -> (bf16 hi, bf16 lo) split:  hi = bf16(v), lo = bf16(v - f32(hi))
// ---------------------------------------------------------------------------
__global__ void split_kernel(const float* __restrict__ in,
                             __nv_bfloat16* __restrict__ hi,
                             __nv_bfloat16* __restrict__ lo, int n4)
{
    const int i = blockIdx.x * blockDim.x + threadIdx.x;
    if (i >= n4) return;
    const float4 v = ((const float4*)in)[i];
    float vv[4] = {v.x, v.y, v.z, v.w};
    unsigned short h[4], l[4];
#pragma unroll
    for (int j = 0; j < 4; ++j) {
        __nv_bfloat16 hb = __float2bfloat16(vv[j]);
        __nv_bfloat16 lb = __float2bfloat16(vv[j] - __bfloat162float(hb));
        h[j] = *reinterpret_cast<unsigned short*>(&hb);
        l[j] = *reinterpret_cast<unsigned short*>(&lb);
    }
    ((ushort4*)hi)[i] = make_ushort4(h[0], h[1], h[2], h[3]);
    ((ushort4*)lo)[i] = make_ushort4(l[0], l[1], l[2], l[3]);
}

// ---------------------------------------------------------------------------
// W_dec [DIN, DHID] row-major  ->  g_wdecT [DHID, DIN] row-major
// ---------------------------------------------------------------------------
__global__ void transpose_kernel(const float* __restrict__ Wd, float* __restrict__ WT)
{
    __shared__ float t[32][33];
    const int h0 = blockIdx.x << 5;
    const int i0 = blockIdx.y << 5;
    const int tx = threadIdx.x;
    const int ty = threadIdx.y;
#pragma unroll
    for (int r = 0; r < 32; r += 8)
        t[ty + r][tx] = Wd[(size_t)(i0 + ty + r) * DHID + h0 + tx];
    __syncthreads();
#pragma unroll
    for (int r = 0; r < 32; r += 8)
        WT[(size_t)(h0 + ty + r) * DIN + i0 + tx] = t[tx][ty + r];
}

// ---------------------------------------------------------------------------
// HMMA encoder: Z = relu( Xhi*Whi^T + Xhi*Wlo^T + Xlo*Whi^T )
// CTA tile 128x256, 8 warps (2M x 4N), warp tile 64x64, BK=32 elements,
// virtual K=3072 via phase-switched pointers, cp.async.cg 3-stage pipeline.
// ---------------------------------------------------------------------------
__device__ __forceinline__ uint32_t smem_u32(const void* p) {
    uint32_t a;
    asm("{ .reg .u64 t; cvta.to.shared.u64 t, %1; cvt.u32.u64 %0, t; }"
        : "=r"(a) : "l"(p));
    return a;
}
__device__ __forceinline__ void ldsm4(uint32_t* r, uint32_t addr) {
    asm volatile("ldmatrix.sync.aligned.m8n8.x4.shared.b16 {%0,%1,%2,%3}, [%4];\n"
        : "=r"(r[0]), "=r"(r[1]), "=r"(r[2]), "=r"(r[3]) : "r"(addr));
}
__device__ __forceinline__ void mma16816(float* c, uint32_t a0, uint32_t a1,
                                         uint32_t a2, uint32_t a3,
                                         uint32_t b0, uint32_t b1) {
    asm volatile(
        "mma.sync.aligned.m16n8k16.row.col.f32.bf16.bf16.f32 "
        "{%0,%1,%2,%3}, {%4,%5,%6,%7}, {%8,%9}, {%0,%1,%2,%3};\n"
        : "+f"(c[0]), "+f"(c[1]), "+f"(c[2]), "+f"(c[3])
        : "r"(a0), "r"(a1), "r"(a2), "r"(a3), "r"(b0), "r"(b1));
}
#define CP_ASYNC16(dst, src) \
    asm volatile("cp.async.cg.shared.global [%0], [%1], 16;\n" :: "r"(dst), "l"(src))
#define CP_COMMIT() asm volatile("cp.async.commit_group;\n" ::: "memory")
#define CP_WAIT1()  asm volatile("cp.async.wait_group 1;\n" ::: "memory")
#define CP_WAIT0()  asm volatile("cp.async.wait_group 0;\n" ::: "memory")

#define BM 128
#define BN 256
#define G_STRIDE 80                       // 64B data + 16B pad, conflict-free
#define STAGE_BYTES ((BM + BN) * G_STRIDE)  // 30720
#define G_STAGES 3
#define G_SMEM (G_STAGES * STAGE_BYTES)   // 92160
#define NCHUNK 96                         // virtual K 3072 / 32

__global__ __launch_bounds__(256, 1) void enc_gemm_hmma(
    const __nv_bfloat16* __restrict__ Xhi, const __nv_bfloat16* __restrict__ Xlo,
    const __nv_bfloat16* __restrict__ Whi, const __nv_bfloat16* __restrict__ Wlo,
    float* __restrict__ Z)
{
    extern __shared__ __align__(16) unsigned char sm[];
    const uint32_t sb = smem_u32(sm);

    const int tid  = threadIdx.x;
    const int lane = tid & 31;
    const int warp = tid >> 5;
    const int Mw = (warp >> 2) << 6;      // 0 / 64
    const int Nw = (warp & 3) << 6;       // 0 / 64 / 128 / 192
    const int bm = blockIdx.y << 7;
    const int bn = blockIdx.x << 8;

    // load mapping: per stage A has 512 16B-chunks, B has 1024.
    const int lrow = tid >> 2;            // 0..63
    const int kc   = tid & 3;             // 16B piece in 64B row

    // ldmatrix per-thread offsets (validated mapping from R7)
    const int tm = (lane & 7) + ((lane >> 3) & 1) * 8;
    const int tk = lane >> 4;
    const uint32_t aOff = (Mw + tm) * G_STRIDE + tk * 16;
    const uint32_t bOff = BM * G_STRIDE + (Nw + tm) * G_STRIDE + tk * 16;

    float acc[4][8][4];
#pragma unroll
    for (int mi = 0; mi < 4; ++mi)
#pragma unroll
        for (int ni = 0; ni < 8; ++ni)
#pragma unroll
            for (int e = 0; e < 4; ++e) acc[mi][ni][e] = 0.0f;

#define ISSUE_LOAD(c, slot)                                                       \
    do {                                                                          \
        const int ph = (c) >> 5;                                                  \
        const int k0 = ((c) & 31) << 5;                                           \
        const __nv_bfloat16* Ap = (ph == 2) ? Xlo : Xhi;                          \
        const __nv_bfloat16* Bp = (ph == 1) ? Wlo : Whi;                          \
        const uint32_t base = sb + (slot) * STAGE_BYTES;                          \
        _Pragma("unroll")                                                         \
        for (int u = 0; u < 2; ++u) {                                             \
            const int r = lrow + u * 64;                                          \
            CP_ASYNC16(base + r * G_STRIDE + kc * 16,                             \
                       Ap + (size_t)(bm + r) * DIN + k0 + kc * 8);                \
        }                                                                         \
        _Pragma("unroll")                                                         \
        for (int u = 0; u < 4; ++u) {                                             \
            const int r = lrow + u * 64;                                          \
            CP_ASYNC16(base + BM * G_STRIDE + r * G_STRIDE + kc * 16,             \
                       Bp + (size_t)(bn + r) * DIN + k0 + kc * 8);                \
        }                                                                         \
    } while (0)

    // prologue: stages 0,1
    ISSUE_LOAD(0, 0); CP_COMMIT();
    ISSUE_LOAD(1, 1); CP_COMMIT();

    for (int c = 0; c < NCHUNK; ++c) {
        if (c + 1 < NCHUNK) CP_WAIT1(); else CP_WAIT0();
        __syncthreads();
        if (c + 2 < NCHUNK) { ISSUE_LOAD(c + 2, (c + 2) % 3); CP_COMMIT(); }

        const uint32_t base = sb + (c % 3) * STAGE_BYTES;
#pragma unroll
        for (int ks = 0; ks < 2; ++ks) {
            uint32_t a[4][4], b[4][4];
#pragma unroll
            for (int mi = 0; mi < 4; ++mi)
                ldsm4(a[mi], base + aOff + mi * (16 * G_STRIDE) + ks * 32);
#pragma unroll
            for (int nb = 0; nb < 4; ++nb)
                ldsm4(b[nb], base + bOff + nb * (16 * G_STRIDE) + ks * 32);
#pragma unroll
            for (int mi = 0; mi < 4; ++mi)
#pragma unroll
                for (int nb = 0; nb < 4; ++nb) {
                    mma16816(acc[mi][2 * nb],     a[mi][0], a[mi][1], a[mi][2], a[mi][3],
                             b[nb][0], b[nb][2]);
                    mma16816(acc[mi][2 * nb + 1], a[mi][0], a[mi][1], a[mi][2], a[mi][3],
                             b[nb][1], b[nb][3]);
                }
        }
    }
#undef ISSUE_LOAD

    // epilogue: relu + store
    const int er = lane >> 2;
    const int ec = (lane & 3) << 1;
#pragma unroll
    for (int mi = 0; mi < 4; ++mi) {
        const size_t r0 = (size_t)(bm + Mw + mi * 16 + er);
        float* z0 = Z + r0 * DHID + bn + Nw + ec;
        float* z1 = z0 + (size_t)8 * DHID;
#pragma unroll
        for (int ni = 0; ni < 8; ++ni) {
            float2 v0, v1;
            v0.x = fmaxf(acc[mi][ni][0], 0.0f);
            v0.y = fmaxf(acc[mi][ni][1], 0.0f);
            v1.x = fmaxf(acc[mi][ni][2], 0.0f);
            v1.y = fmaxf(acc[mi][ni][3], 0.0f);
            *(float2*)(z0 + ni * 8) = v0;
            *(float2*)(z1 + ni * 8) = v1;
        }
    }
}

// ---------------------------------------------------------------------------
// Per-row top-NCAND candidates, barrier-free inner loop.
// One CTA per row. Each warp extracts its local top-48 (of its 2048 owned
// elements) with shfl-only reduction + per-lane top-3 cache; warp 0 merges the
// 8 sorted lists. Also zero-fills the dense z_sparse row.
// ---------------------------------------------------------------------------
__global__ __launch_bounds__(256) void topk_kernel(const float* __restrict__ Z,
                                                   float* __restrict__ Zsp,
                                                   float* __restrict__ cvg,
                                                   int* __restrict__ cig,
                                                   int write_zsp)
{
    extern __shared__ float s[];                 // DHID floats = 64 KB
    __shared__ float wlv[8][NCAND + 1];
    __shared__ int   wli[8][NCAND + 1];

    const int tid  = threadIdx.x;
    const int lane = tid & 31;
    const int w    = tid >> 5;
    const size_t rowoff = (size_t)blockIdx.x * DHID;

    const float4* zr = (const float4*)(Z + rowoff);
    float4* sv4 = (float4*)s;
#pragma unroll
    for (int j = 0; j < 16; ++j) {
        const int q = j * 256 + tid;
        sv4[q] = zr[q];
    }
    if (write_zsp) {
        float4 zero = make_float4(0.f, 0.f, 0.f, 0.f);
        float4* zo = (float4*)(Zsp + rowoff);
#pragma unroll
        for (int j = 0; j < 16; ++j)
            zo[j * 256 + tid] = zero;
    }
    __syncthreads();

    // per-lane top-3 over owned elements {tid + 256j}  (z >= 0 after relu)
    float v1 = -3.f, v2 = -3.f, v3 = -3.f;
    int   i1 = 0,    i2 = 0,    i3 = 0;
#pragma unroll 8
    for (int j = 0; j < 64; ++j) {
        const int idx = tid + (j << 8);
        const float v = s[idx];
        if (v > v3) {
            if (v > v2) {
                v3 = v2; i3 = i2;
                if (v > v1) { v2 = v1; i2 = i1; v1 = v; i1 = idx; }
                else        { v2 = v;  i2 = idx; }
            } else { v3 = v; i3 = idx; }
        }
    }

    // warp-local top-48 extraction (no block barriers)
    for (int it = 0; it < NCAND; ++it) {
        float bv = v1; int bi = i1;
#pragma unroll
        for (int o = 16; o; o >>= 1) {
            const float vv = __shfl_xor_sync(0xFFFFFFFFu, bv, o);
            const int   ii = __shfl_xor_sync(0xFFFFFFFFu, bi, o);
            if (vv > bv || (vv == bv && ii < bi)) { bv = vv; bi = ii; }
        }
        if (lane == 0) { wlv[w][it] = bv; wli[w][it] = bi; }
        if (bi == i1) {                       // owner lane (indices unique)
            s[bi] = -2.0f;
            v1 = v2; i1 = i2; v2 = v3; i2 = i3; v3 = -3.0f; i3 = 0;
            if (v1 < -2.5f) {                 // cache empty: rescan
                v1 = v2 = v3 = -3.0f;
#pragma unroll 8
                for (int j = 0; j < 64; ++j) {
                    const int idx = tid + (j << 8);
                    const float v = s[idx];
                    if (v >= 0.0f && v > v3) {
                        if (v > v2) {
                            v3 = v2; i3 = i2;
                            if (v > v1) { v2 = v1; i2 = i1; v1 = v; i1 = idx; }
                            else        { v2 = v;  i2 = idx; }
                        } else { v3 = v; i3 = idx; }
                    }
                }
            }
        }
    }
    if (lane == 0) { wlv[w][NCAND] = -3.0f; wli[w][NCAND] = -1; }
    __syncthreads();

    // warp 0: 8-way merge of sorted lists -> global top-48
    if (w == 0) {
        int ptr = 0;
        float hv = -3.0f; int hi_ = -1;
        if (lane < 8) { hv = wlv[lane][0]; hi_ = wli[lane][0]; }
        for (int it = 0; it < NCAND; ++it) {
            float bv = hv; int bi = hi_;
#pragma unroll
            for (int o = 16; o; o >>= 1) {
                const float vv = __shfl_xor_sync(0xFFFFFFFFu, bv, o);
                const int   ii = __shfl_xor_sync(0xFFFFFFFFu, bi, o);
                if (vv > bv || (vv == bv && ii < bi)) { bv = vv; bi = ii; }
            }
            if (lane == 0) {
                cvg[blockIdx.x * NCAND + it] = bv;
                cig[blockIdx.x * NCAND + it] = bi;
            }
            if (lane < 8 && hi_ == bi) {      // winning list head advances
                ++ptr;
                hv = wlv[lane][ptr]; hi_ = wli[lane][ptr];
            }
        }
    }
}

// ---------------------------------------------------------------------------
// Exact re-rank: recompute the NCAND candidate dot products per row in fp64
// (from the original fp32 inputs), select the true top-TOPK, write (val, idx)
// and scatter z_sparse.
// ---------------------------------------------------------------------------
__global__ __launch_bounds__(256) void refine_kernel(const float* __restrict__ X,
                                                     const float* __restrict__ W,
                                                     const float* __restrict__ cvg,
                                                     const int* __restrict__ cig,
                                                     float* __restrict__ Zsp,
                                                     float* __restrict__ tvg,
                                                     int* __restrict__ tig,
                                                     int write_zsp)
{
    __shared__ float  sx[DIN];
    __shared__ double dres[NCAND];
    __shared__ float  scv[NCAND];
    __shared__ int    sci[NCAND];

    const int tid  = threadIdx.x;
    const int row  = blockIdx.x;
    const int lane = tid & 31;
    const int w    = tid >> 5;

    for (int j = tid; j < DIN; j += 256)
        sx[j] = X[(size_t)row * DIN + j];
    if (tid < NCAND) {
        scv[tid] = cvg[row * NCAND + tid];
        sci[tid] = cig[row * NCAND + tid];
    }
    __syncthreads();

    for (int c = w; c < NCAND; c += 8) {
        const float* wr = W + ((size_t)sci[c] << 10);
        double a0 = 0.0, a1 = 0.0;
#pragma unroll
        for (int j = 0; j < DIN / 64; ++j) {
            const int e = lane + (j << 6);
            a0 += (double)sx[e]      * (double)wr[e];
            a1 += (double)sx[e + 32] * (double)wr[e + 32];
        }
        double acc = a0 + a1;
#pragma unroll
        for (int o = 16; o; o >>= 1)
            acc += __shfl_down_sync(0xFFFFFFFFu, acc, o);
        if (lane == 0) dres[c] = acc;
    }
    __syncthreads();

    if (tid < NCAND) {
        const double v = dres[tid];
        int rank = 0;
#pragma unroll 8
        for (int j = 0; j < NCAND; ++j) {
            const double u = dres[j];
            if (u > v || (u == v && j < tid)) ++rank;
        }
        if (rank < TOPK) {
            tvg[row * TOPK + rank] = scv[tid];
            tig[row * TOPK + rank] = sci[tid];
            if (write_zsp)
                Zsp[(size_t)row * DHID + sci[tid]] = scv[tid];
        }
    }
}

// ---------------------------------------------------------------------------
// Decoder: x_hat[n,:] = sum_k tv[n,k] * WdT[ti[n,k], :]   (one CTA per row)
// ---------------------------------------------------------------------------
__global__ __launch_bounds__(256) void dec_kernel(const float* __restrict__ WT,
                                                  const float* __restrict__ tvg,
                                                  const int* __restrict__ tig,
                                                  float* __restrict__ xhat)
{
    __shared__ float sv[TOPK];
    __shared__ int   si[TOPK];
    const int tid = threadIdx.x;
    const int row = blockIdx.x;
    if (tid < TOPK) {
        sv[tid] = tvg[row * TOPK + tid];
        si[tid] = tig[row * TOPK + tid];
    }
    __syncthreads();

    const int c = tid << 2;
    float4 acc = make_float4(0.f, 0.f, 0.f, 0.f);
#pragma unroll
    for (int k = 0; k < TOPK; ++k) {
        const float v = sv[k];
        const float4 w = *(const float4*)(WT + ((size_t)si[k] << 10) + c);
        acc.x += v * w.x; acc.y += v * w.y;
        acc.z += v * w.z; acc.w += v * w.w;
    }
    *(float4*)(xhat + ((size_t)row << 10) + c) = acc;
}

// ---------------------------------------------------------------------------
// active = mean_n ( count_k(top-k val > 0) )
// ---------------------------------------------------------------------------
__global__ void active_kernel(const float* __restrict__ tvg, float* __restrict__ act)
{
    __shared__ int sc[256];
    const int tid = threadIdx.x;
    int c = 0;
    for (int i = tid; i < NROWS * TOPK; i += 256)
        c += (tvg[i] > 0.0f) ? 1 : 0;
    sc[tid] = c;
    __syncthreads();
    for (int o = 128; o; o >>= 1) {
        if (tid < o) sc[tid] += sc[tid + o];
        __syncthreads();
    }
    if (tid == 0) act[0] = (float)sc[0] / (float)NROWS;
}

// ---------------------------------------------------------------------------
// Launch
// ---------------------------------------------------------------------------
extern "C" void kernel_launch(void* const* d_in, const int* in_sizes, int n_in,
                              void* d_out, int out_size)
{
    (void)in_sizes; (void)n_in;
    const float* x  = (const float*)d_in[0];
    const float* We = (const float*)d_in[1];
    const float* Wd = (const float*)d_in[2];
    float* out = (float*)d_out;

    __nv_bfloat16 *g_xh, *g_xl, *g_wh, *g_wl;
    cudaGetSymbolAddress((void**)&g_xh, g_xhi);
    cudaGetSymbolAddress((void**)&g_xl, g_xlo);
    cudaGetSymbolAddress((void**)&g_wh, g_whi);
    cudaGetSymbolAddress((void**)&g_wl, g_wlo);
    float* g_wt;  cudaGetSymbolAddress((void**)&g_wt,  g_wdecT);
    float* g_tvp; cudaGetSymbolAddress((void**)&g_tvp, g_tv);
    int*   g_tip; cudaGetSymbolAddress((void**)&g_tip, g_ti);
    float* g_cvp; cudaGetSymbolAddress((void**)&g_cvp, g_cv);
    int*   g_cip; cudaGetSymbolAddress((void**)&g_cip, g_ci);
    float* g_zp;  cudaGetSymbolAddress((void**)&g_zp,  g_zfb);

    const long long XH = (long long)NROWS * DIN;        // 8388608
    const long long ZZ = (long long)NROWS * DHID;       // 134217728
    const long long os = (long long)out_size;

    // Output layout: [x_hat | z_sparse | z | active] flat concat.
    float* xhat = out;
    float* zsp  = nullptr;
    float* z    = nullptr;
    float* act  = nullptr;
    if (os >= XH + 2 * ZZ) {
        zsp = out + XH;
        z   = out + XH + ZZ;
        if (os > XH + 2 * ZZ) act = out + XH + 2 * ZZ;
    } else if (os >= XH + ZZ) {
        zsp = out + XH;
    }
    if (!z) z = g_zp;

    cudaFuncSetAttribute(topk_kernel,
                         cudaFuncAttributeMaxDynamicSharedMemorySize, DHID * 4);
    cudaFuncSetAttribute(enc_gemm_hmma,
                         cudaFuncAttributeMaxDynamicSharedMemorySize, G_SMEM);

    // 1. bf16 hi/lo splits of X and W_enc
    split_kernel<<<(NROWS * DIN / 4 + 255) / 256, 256>>>(x, g_xh, g_xl, NROWS * DIN / 4);
    split_kernel<<<(DHID * DIN / 4 + 255) / 256, 256>>>(We, g_wh, g_wl, DHID * DIN / 4);

    // 2. transpose W_dec (independent; needed by decoder)
    transpose_kernel<<<dim3(DHID / 32, DIN / 32), dim3(32, 8)>>>(Wd, g_wt);

    // 3. HMMA encoder GEMM (3-pass bf16 emulated fp32) + relu -> z
    enc_gemm_hmma<<<dim3(DHID / BN, NROWS / BM), 256, G_SMEM>>>(
        g_xh, g_xl, g_wh, g_wl, z);

    // 4. per-row top-NCAND candidates (+ zero-fill z_sparse)
    topk_kernel<<<NROWS, 256, DHID * 4>>>(z, zsp ? zsp : z, g_cvp, g_cip,
                                          zsp != nullptr ? 1 : 0);

    // 5. exact fp64 re-rank of candidates -> true top-32, scatter z_sparse
    refine_kernel<<<NROWS, 256>>>(x, We, g_cvp, g_cip,
                                  zsp ? zsp : z, g_tvp, g_tip,
                                  zsp != nullptr ? 1 : 0);

    // 6. sparse decoder -> x_hat
    dec_kernel<<<NROWS, 256>>>(g_wt, g_tvp, g_tip, xhat);

    // 7. active scalar
    if (act) active_kernel<<<1, 256>>>(g_tvp, act);
}